// round 2
// baseline (speedup 1.0000x reference)
#include <cuda_runtime.h>

#define N_NODES 100000
#define E_EDGES 1600000
#define B_GRAPHS 64
#define MAXF 256

// ---- scratch (no allocation allowed) ----
__device__ float g_bufA[N_NODES * MAXF];
__device__ float g_bufB[N_NODES * MAXF];
__device__ float g_h[N_NODES * MAXF];
__device__ float g_deg[N_NODES];
__device__ float g_dinv[N_NODES];
__device__ float g_sums[B_GRAPHS * MAXF];
__device__ float g_cnt[B_GRAPHS];
__device__ int   g_mode;   // 1 => indices are int64 (read low word), 0 => int32

// index load honoring detected dtype
__device__ __forceinline__ int load_idx(const int* __restrict__ p, long long elem) {
    return g_mode ? p[2 * elem] : p[(int)elem];
}

// Detect whether edge_index is int64 or int32. Values are in [0, 100000) so for
// int64 every high word is 0; for int32 the odd words are random node ids
// (probability of 64 consecutive zeros ~ 0).
__global__ void detect_mode_kernel(const int* __restrict__ ei) {
    if (threadIdx.x == 0 && blockIdx.x == 0) {
        int allzero = 1;
        for (int i = 0; i < 64; i++) {
            if (ei[2 * i + 1] != 0) { allzero = 0; break; }
        }
        g_mode = allzero;
    }
}

__global__ void deg_init_kernel() {
    int n = blockIdx.x * blockDim.x + threadIdx.x;
    if (n < N_NODES) g_deg[n] = 1.0f;   // +1 self loop
}

__global__ void deg_count_kernel(const int* __restrict__ ei) {
    int e = blockIdx.x * blockDim.x + threadIdx.x;
    if (e < E_EDGES) {
        int dst = load_idx(ei, (long long)E_EDGES + e);
        atomicAdd(&g_deg[dst], 1.0f);
    }
}

__global__ void dinv_kernel() {
    int n = blockIdx.x * blockDim.x + threadIdx.x;
    if (n < N_NODES) g_dinv[n] = rsqrtf(g_deg[n]);
}

// h = (relu?)in @ W ; each thread computes 8 consecutive output features of one node.
__global__ void matmul_kernel(const float* __restrict__ in, const float* __restrict__ W,
                              float* __restrict__ h, int in_dim, int out_dim, int relu_in) {
    int out_q = out_dim >> 3;                 // groups of 8 features
    int t = blockIdx.x * blockDim.x + threadIdx.x;
    int total = N_NODES * out_q;
    if (t >= total) return;
    int n  = t / out_q;
    int f0 = (t - n * out_q) << 3;

    const float* xr = in + (long long)n * in_dim;
    float acc0 = 0.f, acc1 = 0.f, acc2 = 0.f, acc3 = 0.f;
    float acc4 = 0.f, acc5 = 0.f, acc6 = 0.f, acc7 = 0.f;
    for (int k = 0; k < in_dim; k++) {
        float xv = xr[k];
        if (relu_in) xv = fmaxf(xv, 0.f);
        const float4 w0 = *reinterpret_cast<const float4*>(&W[(long long)k * out_dim + f0]);
        const float4 w1 = *reinterpret_cast<const float4*>(&W[(long long)k * out_dim + f0 + 4]);
        acc0 += xv * w0.x; acc1 += xv * w0.y; acc2 += xv * w0.z; acc3 += xv * w0.w;
        acc4 += xv * w1.x; acc5 += xv * w1.y; acc6 += xv * w1.z; acc7 += xv * w1.w;
    }
    float* hp = h + (long long)n * out_dim + f0;
    *reinterpret_cast<float4*>(hp)     = make_float4(acc0, acc1, acc2, acc3);
    *reinterpret_cast<float4*>(hp + 4) = make_float4(acc4, acc5, acc6, acc7);
}

// agg = h * dinv^2 + b   (fuses zero-init + self-loop + bias)
__global__ void init_agg_kernel(const float* __restrict__ h, const float* __restrict__ b,
                                float* __restrict__ agg, int dim) {
    int t = blockIdx.x * blockDim.x + threadIdx.x;
    int total = N_NODES * dim;
    if (t >= total) return;
    int n = t / dim;
    int f = t - n * dim;
    float di = g_dinv[n];
    agg[t] = h[t] * di * di + b[f];
}

// warp per edge: agg[dst] += h[src] * dinv[src]*dinv[dst]
__global__ void scatter_kernel(const float* __restrict__ h, float* __restrict__ agg,
                               const int* __restrict__ ei, int dim) {
    int t = blockIdx.x * blockDim.x + threadIdx.x;
    int lane = t & 31;
    long long e = (long long)(t >> 5);
    if (e >= E_EDGES) return;
    int src = load_idx(ei, e);
    int dst = load_idx(ei, E_EDGES + e);
    float norm = g_dinv[src] * g_dinv[dst];
    const float* hs = h + (long long)src * dim;
    float* ad = agg + (long long)dst * dim;
    for (int f = lane; f < dim; f += 32)
        atomicAdd(&ad[f], hs[f] * norm);
}

__global__ void zero_pool_kernel() {
    int t = blockIdx.x * blockDim.x + threadIdx.x;
    if (t < B_GRAPHS * MAXF) g_sums[t] = 0.f;
    if (t < B_GRAPHS) g_cnt[t] = 0.f;
}

__global__ void cnt_kernel(const int* __restrict__ batch_p) {
    int n = blockIdx.x * blockDim.x + threadIdx.x;
    if (n < N_NODES) atomicAdd(&g_cnt[load_idx(batch_p, n)], 1.0f);
}

// batch is sorted: each block owns 256 consecutive nodes; thread f accumulates
// feature f locally and flushes with one atomic per segment change.
__global__ void pool_kernel(const float* __restrict__ in, const int* __restrict__ batch_p) {
    int f = threadIdx.x;                 // 256 threads = 256 features
    int start = blockIdx.x * 256;
    float acc = 0.f;
    int cur_b = -1;
    for (int i = 0; i < 256; i++) {
        int n = start + i;
        if (n >= N_NODES) break;
        int b = load_idx(batch_p, n);
        if (b != cur_b) {
            if (cur_b >= 0) atomicAdd(&g_sums[cur_b * MAXF + f], acc);
            acc = 0.f; cur_b = b;
        }
        acc += fmaxf(in[(long long)n * MAXF + f], 0.f);   // relu of layer-4 output fused here
    }
    if (cur_b >= 0) atomicAdd(&g_sums[cur_b * MAXF + f], acc);
}

// one block per graph: mean, fc1+relu, fc2, log_softmax
__global__ void head_kernel(const float* __restrict__ fc1_w, const float* __restrict__ fc1_b,
                            const float* __restrict__ fc2_w, const float* __restrict__ fc2_b,
                            float* __restrict__ out) {
    int g = blockIdx.x;
    __shared__ float pooled[256];
    __shared__ float h1[100];
    __shared__ float logits[10];
    float c = fmaxf(g_cnt[g], 1.0f);
    for (int f = threadIdx.x; f < 256; f += blockDim.x)
        pooled[f] = g_sums[g * MAXF + f] / c;
    __syncthreads();
    for (int j = threadIdx.x; j < 100; j += blockDim.x) {
        float a = fc1_b[j];
        for (int k = 0; k < 256; k++) a += pooled[k] * fc1_w[k * 100 + j];
        h1[j] = fmaxf(a, 0.f);
    }
    __syncthreads();
    for (int j = threadIdx.x; j < 10; j += blockDim.x) {
        float a = fc2_b[j];
        for (int k = 0; k < 100; k++) a += h1[k] * fc2_w[k * 10 + j];
        logits[j] = a;
    }
    __syncthreads();
    if (threadIdx.x == 0) {
        float m = -1e30f;
        for (int j = 0; j < 10; j++) m = fmaxf(m, logits[j]);
        float s = 0.f;
        for (int j = 0; j < 10; j++) s += expf(logits[j] - m);
        float lse = m + logf(s);
        for (int j = 0; j < 10; j++) out[g * 10 + j] = logits[j] - lse;
    }
}

static inline int cdiv(long long a, int b) { return (int)((a + b - 1) / b); }

static void run_layer(const float* in, int in_dim, int out_dim, int relu_in,
                      const float* W, const float* b,
                      float* h, float* agg, const int* ei) {
    matmul_kernel<<<cdiv((long long)N_NODES * (out_dim >> 3), 256), 256>>>(in, W, h, in_dim, out_dim, relu_in);
    init_agg_kernel<<<cdiv((long long)N_NODES * out_dim, 256), 256>>>(h, b, agg, out_dim);
    scatter_kernel<<<cdiv((long long)E_EDGES * 32, 256), 256>>>(h, agg, ei, out_dim);
}

extern "C" void kernel_launch(void* const* d_in, const int* in_sizes, int n_in,
                              void* d_out, int out_size) {
    const float* x      = (const float*)d_in[0];
    const int*   ei     = (const int*)d_in[1];
    const int*   batch  = (const int*)d_in[2];
    const float* W1 = (const float*)d_in[3];  const float* b1 = (const float*)d_in[4];
    const float* W2 = (const float*)d_in[5];  const float* b2 = (const float*)d_in[6];
    const float* W3 = (const float*)d_in[7];  const float* b3 = (const float*)d_in[8];
    const float* W4 = (const float*)d_in[9];  const float* b4 = (const float*)d_in[10];
    const float* fc1_w = (const float*)d_in[11]; const float* fc1_b = (const float*)d_in[12];
    const float* fc2_w = (const float*)d_in[13]; const float* fc2_b = (const float*)d_in[14];
    float* out = (float*)d_out;

    float *bufA, *bufB, *h;
    cudaGetSymbolAddress((void**)&bufA, g_bufA);
    cudaGetSymbolAddress((void**)&bufB, g_bufB);
    cudaGetSymbolAddress((void**)&h,    g_h);

    detect_mode_kernel<<<1, 32>>>(ei);
    deg_init_kernel<<<cdiv(N_NODES, 256), 256>>>();
    deg_count_kernel<<<cdiv(E_EDGES, 256), 256>>>(ei);
    dinv_kernel<<<cdiv(N_NODES, 256), 256>>>();

    run_layer(x,    5,   32,  0, W1, b1, h, bufA, ei);
    run_layer(bufA, 32,  64,  1, W2, b2, h, bufB, ei);
    run_layer(bufB, 64,  128, 1, W3, b3, h, bufA, ei);
    run_layer(bufA, 128, 256, 1, W4, b4, h, bufB, ei);

    zero_pool_kernel<<<64, 256>>>();
    cnt_kernel<<<cdiv(N_NODES, 256), 256>>>(batch);
    pool_kernel<<<cdiv(N_NODES, 256), 256>>>(bufB, batch);
    head_kernel<<<B_GRAPHS, 128>>>(fc1_w, fc1_b, fc2_w, fc2_b, out);
}

// round 3
// speedup vs baseline: 4.1343x; 4.1343x over previous
#include <cuda_runtime.h>

#define N_NODES 100000
#define E_EDGES 1600000
#define B_GRAPHS 64

// ---- scratch (no allocation allowed) ----
__device__ float g_bufA[N_NODES * 128];   // layer1 out (32), layer3 out (128)
__device__ float g_bufB[N_NODES * 256];   // layer2 out (64), layer4 out (256)
__device__ float g_agg[N_NODES * 128];    // aggregation output (dim 5..128)
__device__ float g_dinv[N_NODES];
__device__ int   g_counts[N_NODES];
__device__ int   g_rowptr[N_NODES + 1];
__device__ int   g_cursor[N_NODES];
__device__ int   g_blocksums[128];
__device__ int   g_csr_src[E_EDGES];
__device__ float g_csr_norm[E_EDGES];
__device__ float g_sums[B_GRAPHS * 256];
__device__ float g_cnt[B_GRAPHS];
__device__ int   g_mode;   // 1 => indices int64 (read low words), 0 => int32

__device__ __forceinline__ int load_idx(const int* __restrict__ p, long long elem) {
    return g_mode ? p[2 * elem] : p[(int)elem];
}

__global__ void detect_mode_kernel(const int* __restrict__ ei) {
    if (threadIdx.x == 0 && blockIdx.x == 0) {
        int allzero = 1;
        for (int i = 0; i < 64; i++)
            if (ei[2 * i + 1] != 0) { allzero = 0; break; }
        g_mode = allzero;
    }
}

__global__ void zero_kernel() {
    int t = blockIdx.x * blockDim.x + threadIdx.x;
    if (t < N_NODES) g_counts[t] = 0;
    if (t < B_GRAPHS * 256) g_sums[t] = 0.f;
}

__global__ void hist_kernel(const int* __restrict__ ei) {
    int e = blockIdx.x * blockDim.x + threadIdx.x;
    if (e < E_EDGES) atomicAdd(&g_counts[load_idx(ei, (long long)E_EDGES + e)], 1);
}

__global__ void dinv_kernel() {
    int n = blockIdx.x * blockDim.x + threadIdx.x;
    if (n < N_NODES) g_dinv[n] = rsqrtf((float)g_counts[n] + 1.0f);
}

// ---- scan (Hillis-Steele, 1024/block) ----
__global__ void scan1_kernel() {
    __shared__ int s[1024];
    int t = threadIdx.x;
    int i = blockIdx.x * 1024 + t;
    s[t] = (i < N_NODES) ? g_counts[i] : 0;
    __syncthreads();
    for (int d = 1; d < 1024; d <<= 1) {
        int x = (t >= d) ? s[t - d] : 0;
        __syncthreads();
        s[t] += x;
        __syncthreads();
    }
    if (i < N_NODES) g_rowptr[i + 1] = s[t];      // per-block inclusive (no offset yet)
    if (t == 1023) g_blocksums[blockIdx.x] = s[t];
}

__global__ void scan2_kernel(int nblocks) {
    __shared__ int s[128];
    int t = threadIdx.x;
    s[t] = (t < nblocks) ? g_blocksums[t] : 0;
    __syncthreads();
    for (int d = 1; d < 128; d <<= 1) {
        int x = (t >= d) ? s[t - d] : 0;
        __syncthreads();
        s[t] += x;
        __syncthreads();
    }
    if (t < nblocks) g_blocksums[t] = s[t];
}

__global__ void scan3_kernel() {
    int t = threadIdx.x;
    int i = blockIdx.x * 1024 + t;
    if (i >= N_NODES) return;
    int off = (blockIdx.x > 0) ? g_blocksums[blockIdx.x - 1] : 0;
    int inc = g_rowptr[i + 1] + off;
    g_rowptr[i + 1] = inc;
    g_cursor[i] = inc - g_counts[i];     // exclusive start
    if (i == 0) g_rowptr[0] = 0;
}

__global__ void fill_kernel(const int* __restrict__ ei) {
    int e = blockIdx.x * blockDim.x + threadIdx.x;
    if (e >= E_EDGES) return;
    int src = load_idx(ei, e);
    int dst = load_idx(ei, (long long)E_EDGES + e);
    int pos = atomicAdd(&g_cursor[dst], 1);
    g_csr_src[pos] = src;
    g_csr_norm[pos] = g_dinv[src] * g_dinv[dst];
}

// ---- aggregation: out[n] = sum_{e->n} act[src]*norm + act[n]*dinv[n]^2 ----
// small-dim (5): one thread per node
__global__ void agg_dim5(const float* __restrict__ act, float* __restrict__ out) {
    int n = blockIdx.x * blockDim.x + threadIdx.x;
    if (n >= N_NODES) return;
    float dn = g_dinv[n]; dn *= dn;
    float a0 = act[n*5+0]*dn, a1 = act[n*5+1]*dn, a2 = act[n*5+2]*dn,
          a3 = act[n*5+3]*dn, a4 = act[n*5+4]*dn;
    int s = g_rowptr[n], e = g_rowptr[n+1];
    for (int j = s; j < e; j++) {
        int src = g_csr_src[j];
        float nm = g_csr_norm[j];
        const float* p = act + (size_t)src * 5;
        a0 += p[0]*nm; a1 += p[1]*nm; a2 += p[2]*nm; a3 += p[3]*nm; a4 += p[4]*nm;
    }
    float* o = out + (size_t)n * 5;
    o[0]=a0; o[1]=a1; o[2]=a2; o[3]=a3; o[4]=a4;
}

// warp per node, DIM multiple of 32
template<int DIM>
__global__ void agg_warp(const float* __restrict__ act, float* __restrict__ out) {
    int w = (blockIdx.x * blockDim.x + threadIdx.x) >> 5;
    if (w >= N_NODES) return;
    int lane = threadIdx.x & 31;
    constexpr int R = DIM / 32;
    float acc[R];
    float dn = g_dinv[w]; dn *= dn;
    const float* self = act + (size_t)w * DIM + lane;
    #pragma unroll
    for (int i = 0; i < R; i++) acc[i] = self[32*i] * dn;
    int s = g_rowptr[w], e = g_rowptr[w+1];
    for (int j = s; j < e; j++) {
        int src = g_csr_src[j];
        float nm = g_csr_norm[j];
        const float* p = act + (size_t)src * DIM + lane;
        #pragma unroll
        for (int i = 0; i < R; i++) acc[i] += p[32*i] * nm;
    }
    float* o = out + (size_t)w * DIM + lane;
    #pragma unroll
    for (int i = 0; i < R; i++) o[32*i] = acc[i];
}

// ---- GEMM layer1: [N,5] @ [5,32] + b, relu ----
__global__ void gemm5_32(const float* __restrict__ in, const float* __restrict__ W,
                         const float* __restrict__ b, float* __restrict__ out) {
    int n = blockIdx.x * blockDim.x + threadIdx.x;
    if (n >= N_NODES) return;
    float4 acc[8];
    #pragma unroll
    for (int j = 0; j < 8; j++) acc[j] = *(const float4*)&b[j*4];
    const float* xr = in + (size_t)n * 5;
    #pragma unroll
    for (int k = 0; k < 5; k++) {
        float xv = xr[k];
        #pragma unroll
        for (int j = 0; j < 8; j++) {
            float4 w = *(const float4*)&W[k*32 + j*4];
            acc[j].x += xv*w.x; acc[j].y += xv*w.y; acc[j].z += xv*w.z; acc[j].w += xv*w.w;
        }
    }
    float* o = out + (size_t)n * 32;
    #pragma unroll
    for (int j = 0; j < 8; j++) {
        float4 r = acc[j];
        r.x = fmaxf(r.x, 0.f); r.y = fmaxf(r.y, 0.f);
        r.z = fmaxf(r.z, 0.f); r.w = fmaxf(r.w, 0.f);
        *(float4*)&o[j*4] = r;
    }
}

// ---- tiled SGEMM: C[M,Nout] = relu(A[M,K] @ W[K,Nout] + b) ----
// BM=128, BN=64, BK=32, 256 threads, 8x4 register tile
#define BM 128
#define BN 64
#define BK 32
__global__ __launch_bounds__(256) void gemm_tiled(
        const float* __restrict__ A, const float* __restrict__ W,
        const float* __restrict__ bias, float* __restrict__ C,
        int K, int Nout) {
    __shared__ float As[BK][BM + 4];
    __shared__ float Bs[BK][BN];
    int bm = blockIdx.x * BM;
    int bn = blockIdx.y * BN;
    int t = threadIdx.x;
    int tx = t & 15, ty = t >> 4;     // tx: 16 n-groups of 4, ty: 16 m-groups of 8
    float acc[8][4];
    #pragma unroll
    for (int i = 0; i < 8; i++)
        #pragma unroll
        for (int j = 0; j < 4; j++) acc[i][j] = 0.f;

    for (int k0 = 0; k0 < K; k0 += BK) {
        #pragma unroll
        for (int i = 0; i < 4; i++) {
            int id = t + i * 256;         // 0..1023
            int m  = id >> 3;
            int kv = (id & 7) << 2;
            float4 v = make_float4(0.f, 0.f, 0.f, 0.f);
            int gm = bm + m;
            if (gm < N_NODES) v = *(const float4*)&A[(size_t)gm * K + k0 + kv];
            As[kv+0][m] = v.x; As[kv+1][m] = v.y; As[kv+2][m] = v.z; As[kv+3][m] = v.w;
        }
        #pragma unroll
        for (int i = 0; i < 2; i++) {
            int id = t + i * 256;         // 0..511
            int kk = id >> 4;
            int nv = (id & 15) << 2;
            *(float4*)&Bs[kk][nv] = *(const float4*)&W[(size_t)(k0 + kk) * Nout + bn + nv];
        }
        __syncthreads();
        #pragma unroll
        for (int k = 0; k < BK; k++) {
            float a[8], b[4];
            *(float4*)&a[0] = *(const float4*)&As[k][ty*8];
            *(float4*)&a[4] = *(const float4*)&As[k][ty*8 + 4];
            *(float4*)&b[0] = *(const float4*)&Bs[k][tx*4];
            #pragma unroll
            for (int i = 0; i < 8; i++)
                #pragma unroll
                for (int j = 0; j < 4; j++)
                    acc[i][j] += a[i] * b[j];
        }
        __syncthreads();
    }
    float4 bb = *(const float4*)&bias[bn + tx*4];
    #pragma unroll
    for (int i = 0; i < 8; i++) {
        int gm = bm + ty*8 + i;
        if (gm < N_NODES) {
            float4 r;
            r.x = fmaxf(acc[i][0] + bb.x, 0.f);
            r.y = fmaxf(acc[i][1] + bb.y, 0.f);
            r.z = fmaxf(acc[i][2] + bb.z, 0.f);
            r.w = fmaxf(acc[i][3] + bb.w, 0.f);
            *(float4*)&C[(size_t)gm * Nout + bn + tx*4] = r;
        }
    }
}

// ---- pooling / head ----
__global__ void cnt_kernel(const int* __restrict__ batch) {
    int g = threadIdx.x;
    if (g >= B_GRAPHS) return;
    int lo0 = 0, hi0 = N_NODES;
    while (lo0 < hi0) { int m = (lo0+hi0)>>1; if (load_idx(batch, m) < g) lo0 = m+1; else hi0 = m; }
    int lo1 = lo0, hi1 = N_NODES;
    while (lo1 < hi1) { int m = (lo1+hi1)>>1; if (load_idx(batch, m) < g+1) lo1 = m+1; else hi1 = m; }
    g_cnt[g] = (float)(hi1 - lo0 >= 0 ? (lo1 - lo0) : 0);
}

// batch sorted: block owns 256 consecutive nodes, thread f accumulates feature f
__global__ void pool_kernel(const float* __restrict__ in, const int* __restrict__ batch) {
    int f = threadIdx.x;
    int start = blockIdx.x * 256;
    float acc = 0.f;
    int cur_b = -1;
    for (int i = 0; i < 256; i++) {
        int n = start + i;
        if (n >= N_NODES) break;
        int b = load_idx(batch, n);
        if (b != cur_b) {
            if (cur_b >= 0) atomicAdd(&g_sums[cur_b * 256 + f], acc);
            acc = 0.f; cur_b = b;
        }
        acc += in[(size_t)n * 256 + f];     // already relu'd
    }
    if (cur_b >= 0) atomicAdd(&g_sums[cur_b * 256 + f], acc);
}

__global__ void head_kernel(const float* __restrict__ fc1_w, const float* __restrict__ fc1_b,
                            const float* __restrict__ fc2_w, const float* __restrict__ fc2_b,
                            float* __restrict__ out) {
    int g = blockIdx.x;
    __shared__ float pooled[256];
    __shared__ float h1[100];
    __shared__ float logits[10];
    float c = fmaxf(g_cnt[g], 1.0f);
    for (int f = threadIdx.x; f < 256; f += blockDim.x)
        pooled[f] = g_sums[g * 256 + f] / c;
    __syncthreads();
    for (int j = threadIdx.x; j < 100; j += blockDim.x) {
        float a = fc1_b[j];
        for (int k = 0; k < 256; k++) a += pooled[k] * fc1_w[k * 100 + j];
        h1[j] = fmaxf(a, 0.f);
    }
    __syncthreads();
    for (int j = threadIdx.x; j < 10; j += blockDim.x) {
        float a = fc2_b[j];
        for (int k = 0; k < 100; k++) a += h1[k] * fc2_w[k * 10 + j];
        logits[j] = a;
    }
    __syncthreads();
    if (threadIdx.x == 0) {
        float m = -1e30f;
        for (int j = 0; j < 10; j++) m = fmaxf(m, logits[j]);
        float s = 0.f;
        for (int j = 0; j < 10; j++) s += expf(logits[j] - m);
        float lse = m + logf(s);
        for (int j = 0; j < 10; j++) out[g * 10 + j] = logits[j] - lse;
    }
}

static inline int cdiv(long long a, int b) { return (int)((a + b - 1) / b); }

extern "C" void kernel_launch(void* const* d_in, const int* in_sizes, int n_in,
                              void* d_out, int out_size) {
    const float* x     = (const float*)d_in[0];
    const int*   ei    = (const int*)d_in[1];
    const int*   batch = (const int*)d_in[2];
    const float* W1 = (const float*)d_in[3];  const float* b1 = (const float*)d_in[4];
    const float* W2 = (const float*)d_in[5];  const float* b2 = (const float*)d_in[6];
    const float* W3 = (const float*)d_in[7];  const float* b3 = (const float*)d_in[8];
    const float* W4 = (const float*)d_in[9];  const float* b4 = (const float*)d_in[10];
    const float* fc1_w = (const float*)d_in[11]; const float* fc1_b = (const float*)d_in[12];
    const float* fc2_w = (const float*)d_in[13]; const float* fc2_b = (const float*)d_in[14];
    float* out = (float*)d_out;

    float *bufA, *bufB, *agg;
    cudaGetSymbolAddress((void**)&bufA, g_bufA);
    cudaGetSymbolAddress((void**)&bufB, g_bufB);
    cudaGetSymbolAddress((void**)&agg,  g_agg);

    const int nscan = cdiv(N_NODES, 1024);   // 98

    detect_mode_kernel<<<1, 32>>>(ei);
    zero_kernel<<<cdiv(N_NODES, 256), 256>>>();
    hist_kernel<<<cdiv(E_EDGES, 256), 256>>>(ei);
    dinv_kernel<<<cdiv(N_NODES, 256), 256>>>();
    scan1_kernel<<<nscan, 1024>>>();
    scan2_kernel<<<1, 128>>>(nscan);
    scan3_kernel<<<nscan, 1024>>>();
    fill_kernel<<<cdiv(E_EDGES, 256), 256>>>(ei);

    // layer 1: agg(x) [N,5] -> gemm -> relu -> bufA [N,32]
    agg_dim5<<<cdiv(N_NODES, 256), 256>>>(x, agg);
    gemm5_32<<<cdiv(N_NODES, 256), 256>>>(agg, W1, b1, bufA);

    // layer 2: agg(bufA) [N,32] -> gemm -> bufB [N,64]
    agg_warp<32><<<cdiv((long long)N_NODES * 32, 256), 256>>>(bufA, agg);
    {
        dim3 grid(cdiv(N_NODES, BM), 64 / BN);
        gemm_tiled<<<grid, 256>>>(agg, W2, b2, bufB, 32, 64);
    }
    // layer 3: agg(bufB) [N,64] -> gemm -> bufA [N,128]
    agg_warp<64><<<cdiv((long long)N_NODES * 32, 256), 256>>>(bufB, agg);
    {
        dim3 grid(cdiv(N_NODES, BM), 128 / BN);
        gemm_tiled<<<grid, 256>>>(agg, W3, b3, bufA, 64, 128);
    }
    // layer 4: agg(bufA) [N,128] -> gemm -> bufB [N,256]
    agg_warp<128><<<cdiv((long long)N_NODES * 32, 256), 256>>>(bufA, agg);
    {
        dim3 grid(cdiv(N_NODES, BM), 256 / BN);
        gemm_tiled<<<grid, 256>>>(agg, W4, b4, bufB, 128, 256);
    }

    cnt_kernel<<<1, 64>>>(batch);
    pool_kernel<<<cdiv(N_NODES, 256), 256>>>(bufB, batch);
    head_kernel<<<B_GRAPHS, 128>>>(fc1_w, fc1_b, fc2_w, fc2_b, out);
}

// round 6
// speedup vs baseline: 4.7696x; 1.1537x over previous
#include <cuda_runtime.h>
#include <cuda_bf16.h>
#include <cstdint>

#define N_NODES 100000
#define E_EDGES 1600000
#define B_GRAPHS 64

// ---- scratch (no allocation allowed) ----
__device__ float g_bufA[N_NODES * 128];   // layer1 out (32), layer3 out (128)
__device__ float g_bufB[N_NODES * 256];   // layer2 out (64), layer4 out (256)
__device__ float g_agg[N_NODES * 128];    // aggregation output (dim 5..128)
__device__ float g_dinv[N_NODES];
__device__ int   g_counts[N_NODES];
__device__ int   g_rowptr[N_NODES + 1];
__device__ int   g_cursor[N_NODES];
__device__ int   g_blocksums[128];
__device__ int   g_csr_src[E_EDGES];
__device__ float g_csr_norm[E_EDGES];
__device__ float g_sums[B_GRAPHS * 256];
__device__ float g_cnt[B_GRAPHS];
__device__ int   g_mode;   // 1 => indices int64 (read low words), 0 => int32

__device__ __forceinline__ int load_idx(const int* __restrict__ p, long long elem) {
    return g_mode ? p[2 * elem] : p[(int)elem];
}

__global__ void detect_mode_kernel(const int* __restrict__ ei) {
    if (threadIdx.x == 0 && blockIdx.x == 0) {
        int allzero = 1;
        for (int i = 0; i < 64; i++)
            if (ei[2 * i + 1] != 0) { allzero = 0; break; }
        g_mode = allzero;
    }
}

__global__ void zero_kernel() {
    int t = blockIdx.x * blockDim.x + threadIdx.x;
    if (t < N_NODES) g_counts[t] = 0;
    if (t < B_GRAPHS * 256) g_sums[t] = 0.f;
}

__global__ void hist_kernel(const int* __restrict__ ei) {
    int e = blockIdx.x * blockDim.x + threadIdx.x;
    if (e < E_EDGES) atomicAdd(&g_counts[load_idx(ei, (long long)E_EDGES + e)], 1);
}

// ---- scan (Hillis-Steele, 1024/block); also computes dinv from counts ----
__global__ void scan1_kernel() {
    __shared__ int s[1024];
    int t = threadIdx.x;
    int i = blockIdx.x * 1024 + t;
    int c = (i < N_NODES) ? g_counts[i] : 0;
    if (i < N_NODES) g_dinv[i] = rsqrtf((float)c + 1.0f);
    s[t] = c;
    __syncthreads();
    for (int d = 1; d < 1024; d <<= 1) {
        int x = (t >= d) ? s[t - d] : 0;
        __syncthreads();
        s[t] += x;
        __syncthreads();
    }
    if (i < N_NODES) g_rowptr[i + 1] = s[t];
    if (t == 1023) g_blocksums[blockIdx.x] = s[t];
}

__global__ void scan2_kernel(int nblocks) {
    __shared__ int s[128];
    int t = threadIdx.x;
    s[t] = (t < nblocks) ? g_blocksums[t] : 0;
    __syncthreads();
    for (int d = 1; d < 128; d <<= 1) {
        int x = (t >= d) ? s[t - d] : 0;
        __syncthreads();
        s[t] += x;
        __syncthreads();
    }
    if (t < nblocks) g_blocksums[t] = s[t];
}

__global__ void scan3_kernel() {
    int t = threadIdx.x;
    int i = blockIdx.x * 1024 + t;
    if (i >= N_NODES) return;
    int off = (blockIdx.x > 0) ? g_blocksums[blockIdx.x - 1] : 0;
    int inc = g_rowptr[i + 1] + off;
    g_rowptr[i + 1] = inc;
    g_cursor[i] = inc - g_counts[i];
    if (i == 0) g_rowptr[0] = 0;
}

__global__ void fill_kernel(const int* __restrict__ ei) {
    int e = blockIdx.x * blockDim.x + threadIdx.x;
    if (e >= E_EDGES) return;
    int src = load_idx(ei, e);
    int dst = load_idx(ei, (long long)E_EDGES + e);
    int pos = atomicAdd(&g_cursor[dst], 1);
    g_csr_src[pos] = src;
    g_csr_norm[pos] = g_dinv[src] * g_dinv[dst];
}

// ---- aggregation ----
__global__ void agg_dim5(const float* __restrict__ act, float* __restrict__ out) {
    int n = blockIdx.x * blockDim.x + threadIdx.x;
    if (n >= N_NODES) return;
    float dn = g_dinv[n]; dn *= dn;
    float a0 = act[n*5+0]*dn, a1 = act[n*5+1]*dn, a2 = act[n*5+2]*dn,
          a3 = act[n*5+3]*dn, a4 = act[n*5+4]*dn;
    int s = g_rowptr[n], e = g_rowptr[n+1];
    for (int j = s; j < e; j++) {
        int src = g_csr_src[j];
        float nm = g_csr_norm[j];
        const float* p = act + (size_t)src * 5;
        a0 += p[0]*nm; a1 += p[1]*nm; a2 += p[2]*nm; a3 += p[3]*nm; a4 += p[4]*nm;
    }
    float* o = out + (size_t)n * 5;
    o[0]=a0; o[1]=a1; o[2]=a2; o[3]=a3; o[4]=a4;
}

// warp per node, 2-edge unroll for MLP
template<int DIM>
__global__ void agg_warp(const float* __restrict__ act, float* __restrict__ out) {
    int w = (blockIdx.x * blockDim.x + threadIdx.x) >> 5;
    if (w >= N_NODES) return;
    int lane = threadIdx.x & 31;
    constexpr int R = DIM / 32;
    float acc[R];
    float dn = g_dinv[w]; dn *= dn;
    const float* self = act + (size_t)w * DIM + lane;
    #pragma unroll
    for (int i = 0; i < R; i++) acc[i] = self[32*i] * dn;
    int s = g_rowptr[w], e = g_rowptr[w+1];
    int j = s;
    for (; j + 2 <= e; j += 2) {
        int s0 = g_csr_src[j], s1 = g_csr_src[j+1];
        float n0 = g_csr_norm[j], n1 = g_csr_norm[j+1];
        const float* p0 = act + (size_t)s0 * DIM + lane;
        const float* p1 = act + (size_t)s1 * DIM + lane;
        #pragma unroll
        for (int i = 0; i < R; i++) {
            float v0 = p0[32*i], v1 = p1[32*i];
            acc[i] += v0 * n0;
            acc[i] += v1 * n1;
        }
    }
    if (j < e) {
        int s0 = g_csr_src[j];
        float n0 = g_csr_norm[j];
        const float* p0 = act + (size_t)s0 * DIM + lane;
        #pragma unroll
        for (int i = 0; i < R; i++) acc[i] += p0[32*i] * n0;
    }
    float* o = out + (size_t)w * DIM + lane;
    #pragma unroll
    for (int i = 0; i < R; i++) o[32*i] = acc[i];
}

// ---- layer 1 GEMM: [N,5] @ [5,32] + b, relu (tiny, SIMT fp32) ----
__global__ void gemm5_32(const float* __restrict__ in, const float* __restrict__ W,
                         const float* __restrict__ b, float* __restrict__ out) {
    int n = blockIdx.x * blockDim.x + threadIdx.x;
    if (n >= N_NODES) return;
    float4 acc[8];
    #pragma unroll
    for (int j = 0; j < 8; j++) acc[j] = *(const float4*)&b[j*4];
    const float* xr = in + (size_t)n * 5;
    #pragma unroll
    for (int k = 0; k < 5; k++) {
        float xv = xr[k];
        #pragma unroll
        for (int j = 0; j < 8; j++) {
            float4 w = *(const float4*)&W[k*32 + j*4];
            acc[j].x += xv*w.x; acc[j].y += xv*w.y; acc[j].z += xv*w.z; acc[j].w += xv*w.w;
        }
    }
    float* o = out + (size_t)n * 32;
    #pragma unroll
    for (int j = 0; j < 8; j++) {
        float4 r = acc[j];
        r.x = fmaxf(r.x, 0.f); r.y = fmaxf(r.y, 0.f);
        r.z = fmaxf(r.z, 0.f); r.w = fmaxf(r.w, 0.f);
        *(float4*)&o[j*4] = r;
    }
}

// ======== tensor-core GEMM with bf16 hi/lo split (error-compensated) ========
// C[M,Nout] = relu(A[M,K] @ W[K,Nout] + bias), fp32 in/out, rel err ~2e-5.
// BM=128, BN=64, BK=64, 256 threads (8 warps x m16), mma.m16n8k16.bf16.

__device__ __forceinline__ void ldsm_x4(uint32_t* r, uint32_t addr) {
    asm volatile("ldmatrix.sync.aligned.m8n8.x4.shared.b16 {%0,%1,%2,%3}, [%4];"
        : "=r"(r[0]), "=r"(r[1]), "=r"(r[2]), "=r"(r[3]) : "r"(addr));
}
__device__ __forceinline__ void ldsm_x2_t(uint32_t* r, uint32_t addr) {
    asm volatile("ldmatrix.sync.aligned.m8n8.x2.trans.shared.b16 {%0,%1}, [%2];"
        : "=r"(r[0]), "=r"(r[1]) : "r"(addr));
}
__device__ __forceinline__ void mma_bf16(float* c, const uint32_t* a, const uint32_t* b) {
    asm volatile("mma.sync.aligned.m16n8k16.row.col.f32.bf16.bf16.f32 "
        "{%0,%1,%2,%3}, {%4,%5,%6,%7}, {%8,%9}, {%0,%1,%2,%3};"
        : "+f"(c[0]), "+f"(c[1]), "+f"(c[2]), "+f"(c[3])
        : "r"(a[0]), "r"(a[1]), "r"(a[2]), "r"(a[3]), "r"(b[0]), "r"(b[1]));
}
__device__ __forceinline__ uint32_t pack_bf16(__nv_bfloat16 a, __nv_bfloat16 b) {
    __nv_bfloat162 t; t.x = a; t.y = b;
    return *reinterpret_cast<uint32_t*>(&t);
}

template<int K>
__global__ __launch_bounds__(256) void gemm_tc(
        const float* __restrict__ A, const float* __restrict__ W,
        const float* __restrict__ bias, float* __restrict__ C, int Nout) {
    constexpr int KT = (K + 63) / 64;             // k-tiles of 64
    __shared__ __align__(16) unsigned char sm[49152];
    unsigned char* As_hi = sm;                    // 128 rows x 128B
    unsigned char* As_lo = sm + 16384;
    unsigned char* Bs_hi = sm + 32768;            // 64 rows x 128B
    unsigned char* Bs_lo = sm + 40960;

    const int bm = blockIdx.x * 128;
    const int bn = blockIdx.y * 64;
    const int tid = threadIdx.x;
    const int wid = tid >> 5, lane = tid & 31;

    float acc[8][4];
    #pragma unroll
    for (int j = 0; j < 8; j++)
        #pragma unroll
        for (int q = 0; q < 4; q++) acc[j][q] = 0.f;

    const uint32_t sa_hi = (uint32_t)__cvta_generic_to_shared(As_hi);
    const uint32_t sa_lo = (uint32_t)__cvta_generic_to_shared(As_lo);
    const uint32_t sb_hi = (uint32_t)__cvta_generic_to_shared(Bs_hi);
    const uint32_t sb_lo = (uint32_t)__cvta_generic_to_shared(Bs_lo);

    for (int kt = 0; kt < KT; kt++) {
        const int kbase = kt * 64;
        // A tile: 128 rows x 64 cols (zero-pad past K or M)
        #pragma unroll
        for (int c = 0; c < 4; c++) {
            int id = tid + c * 256;               // 0..1023 chunks of 8 elems
            int row = id >> 3;
            int ck  = (id & 7) << 3;              // elem col in tile
            int gm = bm + row, gk = kbase + ck;
            float v[8] = {0,0,0,0,0,0,0,0};
            if (gm < N_NODES && gk < K) {
                float4 v0 = *(const float4*)(A + (size_t)gm * K + gk);
                float4 v1 = *(const float4*)(A + (size_t)gm * K + gk + 4);
                v[0]=v0.x; v[1]=v0.y; v[2]=v0.z; v[3]=v0.w;
                v[4]=v1.x; v[5]=v1.y; v[6]=v1.z; v[7]=v1.w;
            }
            uint32_t h[4], l[4];
            #pragma unroll
            for (int q = 0; q < 4; q++) {
                __nv_bfloat16 h0 = __float2bfloat16(v[2*q]);
                __nv_bfloat16 h1 = __float2bfloat16(v[2*q+1]);
                __nv_bfloat16 l0 = __float2bfloat16(v[2*q]   - __bfloat162float(h0));
                __nv_bfloat16 l1 = __float2bfloat16(v[2*q+1] - __bfloat162float(h1));
                h[q] = pack_bf16(h0, h1);
                l[q] = pack_bf16(l0, l1);
            }
            int off = row * 128 + (((ck) * 2) ^ ((row & 7) << 4));
            *(uint4*)(As_hi + off) = make_uint4(h[0], h[1], h[2], h[3]);
            *(uint4*)(As_lo + off) = make_uint4(l[0], l[1], l[2], l[3]);
        }
        // B tile: 64 k-rows x 64 n-cols
        #pragma unroll
        for (int c = 0; c < 2; c++) {
            int id = tid + c * 256;               // 0..511
            int r  = id >> 3;
            int cn = (id & 7) << 3;
            int gk = kbase + r;
            float v[8] = {0,0,0,0,0,0,0,0};
            if (gk < K) {
                float4 v0 = *(const float4*)(W + (size_t)gk * Nout + bn + cn);
                float4 v1 = *(const float4*)(W + (size_t)gk * Nout + bn + cn + 4);
                v[0]=v0.x; v[1]=v0.y; v[2]=v0.z; v[3]=v0.w;
                v[4]=v1.x; v[5]=v1.y; v[6]=v1.z; v[7]=v1.w;
            }
            uint32_t h[4], l[4];
            #pragma unroll
            for (int q = 0; q < 4; q++) {
                __nv_bfloat16 h0 = __float2bfloat16(v[2*q]);
                __nv_bfloat16 h1 = __float2bfloat16(v[2*q+1]);
                __nv_bfloat16 l0 = __float2bfloat16(v[2*q]   - __bfloat162float(h0));
                __nv_bfloat16 l1 = __float2bfloat16(v[2*q+1] - __bfloat162float(h1));
                h[q] = pack_bf16(h0, h1);
                l[q] = pack_bf16(l0, l1);
            }
            int off = r * 128 + (((cn) * 2) ^ ((r & 7) << 4));
            *(uint4*)(Bs_hi + off) = make_uint4(h[0], h[1], h[2], h[3]);
            *(uint4*)(Bs_lo + off) = make_uint4(l[0], l[1], l[2], l[3]);
        }
        __syncthreads();

        const int warp_m = wid * 16;
        #pragma unroll
        for (int kk = 0; kk < 64; kk += 16) {
            // A fragments (hi/lo), canonical ldmatrix.x4 address pattern
            int lr = warp_m + (lane & 15);
            int lc = (kk + (lane >> 4) * 8) * 2;          // byte col
            uint32_t aoff = (uint32_t)(lr * 128 + (lc ^ ((lr & 7) << 4)));
            uint32_t ah[4], al[4];
            ldsm_x4(ah, sa_hi + aoff);
            ldsm_x4(al, sa_lo + aoff);
            int br = kk + (lane & 15);
            #pragma unroll
            for (int j = 0; j < 8; j++) {
                int bc = (j * 8) * 2;                     // byte col
                uint32_t boff = (uint32_t)(br * 128 + (bc ^ ((br & 7) << 4)));
                uint32_t bh[2], bl[2];
                ldsm_x2_t(bh, sb_hi + boff);
                ldsm_x2_t(bl, sb_lo + boff);
                mma_bf16(acc[j], ah, bh);
                mma_bf16(acc[j], ah, bl);
                mma_bf16(acc[j], al, bh);
            }
        }
        __syncthreads();
    }

    // epilogue: bias + relu, canonical C fragment layout
    int r0 = bm + wid * 16 + (lane >> 2);
    int c0 = bn + 2 * (lane & 3);
    #pragma unroll
    for (int j = 0; j < 8; j++) {
        int col = c0 + j * 8;
        float bb0 = bias[col], bb1 = bias[col + 1];
        if (r0 < N_NODES) {
            float2 r;
            r.x = fmaxf(acc[j][0] + bb0, 0.f);
            r.y = fmaxf(acc[j][1] + bb1, 0.f);
            *(float2*)(C + (size_t)r0 * Nout + col) = r;
        }
        if (r0 + 8 < N_NODES) {
            float2 r;
            r.x = fmaxf(acc[j][2] + bb0, 0.f);
            r.y = fmaxf(acc[j][3] + bb1, 0.f);
            *(float2*)(C + (size_t)(r0 + 8) * Nout + col) = r;
        }
    }
}

// ---- pooling / head ----
__global__ void cnt_kernel(const int* __restrict__ batch) {
    int g = threadIdx.x;
    if (g >= B_GRAPHS) return;
    int lo0 = 0, hi0 = N_NODES;
    while (lo0 < hi0) { int m = (lo0+hi0)>>1; if (load_idx(batch, m) < g) lo0 = m+1; else hi0 = m; }
    int lo1 = lo0, hi1 = N_NODES;
    while (lo1 < hi1) { int m = (lo1+hi1)>>1; if (load_idx(batch, m) < g+1) lo1 = m+1; else hi1 = m; }
    g_cnt[g] = (float)(lo1 - lo0);
}

__global__ void pool_kernel(const float* __restrict__ in, const int* __restrict__ batch) {
    int f = threadIdx.x;
    int start = blockIdx.x * 256;
    float acc = 0.f;
    int cur_b = -1;
    for (int i = 0; i < 256; i++) {
        int n = start + i;
        if (n >= N_NODES) break;
        int b = load_idx(batch, n);
        if (b != cur_b) {
            if (cur_b >= 0) atomicAdd(&g_sums[cur_b * 256 + f], acc);
            acc = 0.f; cur_b = b;
        }
        acc += in[(size_t)n * 256 + f];
    }
    if (cur_b >= 0) atomicAdd(&g_sums[cur_b * 256 + f], acc);
}

__global__ void head_kernel(const float* __restrict__ fc1_w, const float* __restrict__ fc1_b,
                            const float* __restrict__ fc2_w, const float* __restrict__ fc2_b,
                            float* __restrict__ out) {
    int g = blockIdx.x;
    __shared__ float pooled[256];
    __shared__ float h1[100];
    __shared__ float logits[10];
    float c = fmaxf(g_cnt[g], 1.0f);
    for (int f = threadIdx.x; f < 256; f += blockDim.x)
        pooled[f] = g_sums[g * 256 + f] / c;
    __syncthreads();
    for (int j = threadIdx.x; j < 100; j += blockDim.x) {
        float a = fc1_b[j];
        for (int k = 0; k < 256; k++) a += pooled[k] * fc1_w[k * 100 + j];
        h1[j] = fmaxf(a, 0.f);
    }
    __syncthreads();
    for (int j = threadIdx.x; j < 10; j += blockDim.x) {
        float a = fc2_b[j];
        for (int k = 0; k < 100; k++) a += h1[k] * fc2_w[k * 10 + j];
        logits[j] = a;
    }
    __syncthreads();
    if (threadIdx.x == 0) {
        float m = -1e30f;
        for (int j = 0; j < 10; j++) m = fmaxf(m, logits[j]);
        float s = 0.f;
        for (int j = 0; j < 10; j++) s += expf(logits[j] - m);
        float lse = m + logf(s);
        for (int j = 0; j < 10; j++) out[g * 10 + j] = logits[j] - lse;
    }
}

static inline int cdiv(long long a, int b) { return (int)((a + b - 1) / b); }

extern "C" void kernel_launch(void* const* d_in, const int* in_sizes, int n_in,
                              void* d_out, int out_size) {
    const float* x     = (const float*)d_in[0];
    const int*   ei    = (const int*)d_in[1];
    const int*   batch = (const int*)d_in[2];
    const float* W1 = (const float*)d_in[3];  const float* b1 = (const float*)d_in[4];
    const float* W2 = (const float*)d_in[5];  const float* b2 = (const float*)d_in[6];
    const float* W3 = (const float*)d_in[7];  const float* b3 = (const float*)d_in[8];
    const float* W4 = (const float*)d_in[9];  const float* b4 = (const float*)d_in[10];
    const float* fc1_w = (const float*)d_in[11]; const float* fc1_b = (const float*)d_in[12];
    const float* fc2_w = (const float*)d_in[13]; const float* fc2_b = (const float*)d_in[14];
    float* out = (float*)d_out;

    float *bufA, *bufB, *agg;
    cudaGetSymbolAddress((void**)&bufA, g_bufA);
    cudaGetSymbolAddress((void**)&bufB, g_bufB);
    cudaGetSymbolAddress((void**)&agg,  g_agg);

    const int nscan = cdiv(N_NODES, 1024);

    detect_mode_kernel<<<1, 32>>>(ei);
    zero_kernel<<<cdiv(N_NODES, 256), 256>>>();
    hist_kernel<<<cdiv(E_EDGES, 256), 256>>>(ei);
    scan1_kernel<<<nscan, 1024>>>();
    scan2_kernel<<<1, 128>>>(nscan);
    scan3_kernel<<<nscan, 1024>>>();
    fill_kernel<<<cdiv(E_EDGES, 256), 256>>>(ei);

    // layer 1
    agg_dim5<<<cdiv(N_NODES, 256), 256>>>(x, agg);
    gemm5_32<<<cdiv(N_NODES, 256), 256>>>(agg, W1, b1, bufA);

    // layer 2: K=32 -> Nout=64
    agg_warp<32><<<cdiv((long long)N_NODES * 32, 256), 256>>>(bufA, agg);
    gemm_tc<32><<<dim3(cdiv(N_NODES, 128), 1), 256>>>(agg, W2, b2, bufB, 64);

    // layer 3: K=64 -> Nout=128
    agg_warp<64><<<cdiv((long long)N_NODES * 32, 256), 256>>>(bufB, agg);
    gemm_tc<64><<<dim3(cdiv(N_NODES, 128), 2), 256>>>(agg, W3, b3, bufA, 128);

    // layer 4: K=128 -> Nout=256
    agg_warp<128><<<cdiv((long long)N_NODES * 32, 256), 256>>>(bufA, agg);
    gemm_tc<128><<<dim3(cdiv(N_NODES, 128), 4), 256>>>(agg, W4, b4, bufB, 256);

    cnt_kernel<<<1, 64>>>(batch);
    pool_kernel<<<cdiv(N_NODES, 256), 256>>>(bufB, batch);
    head_kernel<<<B_GRAPHS, 128>>>(fc1_w, fc1_b, fc2_w, fc2_b, out);
}